// round 2
// baseline (speedup 1.0000x reference)
#include <cuda_runtime.h>
#include <cstdint>

#define NN 12288
#define DD 128
#define TM 64
#define TK 16
#define JSPLIT 4
#define JLEN (NN / JSPLIT)      // 3072
#define NTILES (JLEN / TK)      // 192
#define MTILES (NN / TM)        // 192

// ---------------- scratch (static device memory; no allocation) ----------------
__device__ float g_WT[DD * DD];                    // W transposed (k-major)
__device__ float g_V[(size_t)NN * DD];             // e_new, fp32
__device__ float g_s[NN], g_t[NN];
__device__ float g_Es[NN], g_Et[NN], g_Fs[NN], g_Ft[NN];
__device__ float g_parts[JSPLIT][(size_t)NN * DD]; // partial P@V accumulators
__device__ float g_dparts[JSPLIT][NN];             // partial row denominators

// ---------------- Kernel A0: transpose W into k-major layout ----------------
__global__ void k_transW(const float* __restrict__ W) {
    int i = blockIdx.x * 256 + threadIdx.x;
    if (i < DD * DD) {
        int d = i >> 7, k = i & 127;
        g_WT[k * DD + d] = W[i];
    }
}

// ---------------- Kernel A: e_new = emb @ W^T  (16 rows per block) ----------------
// 256 threads = 8 row-groups (2 rows each) x 32 dim-groups (4 dims each)
//            -> exactly 16 rows x 128 dims, no overlap, no OOB.
__global__ __launch_bounds__(256) void k_enew(const float* __restrict__ emb) {
    const int rb = blockIdx.x * 16;
    const int tid = threadIdx.x;
    __shared__ float es[16][128];

    for (int i = tid; i < 16 * 128; i += 256) {
        int r = i >> 7, k = i & 127;
        es[r][k] = emb[(size_t)(rb + r) * DD + k];
    }
    __syncthreads();

    const int rg = tid >> 5;   // 0..7  -> rows 2*rg, 2*rg+1
    const int dq = tid & 31;   // 0..31 -> dims 4*dq .. 4*dq+3

    float acc[2][4];
    #pragma unroll
    for (int i = 0; i < 2; i++)
        #pragma unroll
        for (int j = 0; j < 4; j++) acc[i][j] = 0.f;

    #pragma unroll 4
    for (int k = 0; k < 128; ++k) {
        float4 wv = *(const float4*)&g_WT[k * DD + 4 * dq];
        float e0 = es[rg * 2 + 0][k];
        float e1 = es[rg * 2 + 1][k];
        acc[0][0] += e0 * wv.x; acc[0][1] += e0 * wv.y; acc[0][2] += e0 * wv.z; acc[0][3] += e0 * wv.w;
        acc[1][0] += e1 * wv.x; acc[1][1] += e1 * wv.y; acc[1][2] += e1 * wv.z; acc[1][3] += e1 * wv.w;
    }

    #pragma unroll
    for (int rr = 0; rr < 2; ++rr) {
        size_t row = (size_t)(rb + rg * 2 + rr) * DD;
        *(float4*)&g_V[row + 4 * dq] = make_float4(acc[rr][0], acc[rr][1], acc[rr][2], acc[rr][3]);
    }
}

// ---------------- Kernel B: per-row scalars s, t and their exps ----------------
__global__ void k_scal(const float* __restrict__ a) {
    const int i = blockIdx.x;
    const int tid = threadIdx.x;  // 128 threads
    float v = g_V[(size_t)i * DD + tid];
    float sp = v * a[tid];
    float tp = v * a[DD + tid];
    #pragma unroll
    for (int off = 16; off; off >>= 1) {
        sp += __shfl_down_sync(0xffffffffu, sp, off);
        tp += __shfl_down_sync(0xffffffffu, tp, off);
    }
    __shared__ float rs[4], rt[4];
    int w = tid >> 5;
    if ((tid & 31) == 0) { rs[w] = sp; rt[w] = tp; }
    __syncthreads();
    if (tid == 0) {
        float s = rs[0] + rs[1] + rs[2] + rs[3];
        float t = rt[0] + rt[1] + rt[2] + rt[3];
        g_s[i] = s; g_Es[i] = expf(s); g_Fs[i] = expf(0.01f * s);
        g_t[i] = t; g_Et[i] = expf(t); g_Ft[i] = expf(0.01f * t);
    }
}

// ---------------- Kernel C: fused mask+softmax-weights + P@V (the heavy one) ----
// Block: 256 threads, 64 rows x 128 dims output, K-tile = 16 j's.
// Thread map: warp w owns dims [16w,16w+16); lane l: rows 4*(l&15).. , dim-half (l>>4).
// Accumulators are packed f32x2 (fma.rn.f32x2 doubles fp32 FMA throughput).
__global__ __launch_bounds__(256, 3) void k_main(const int* __restrict__ adj) {
    const int rb = blockIdx.x * TM;
    const int jsp = blockIdx.y;
    const int tid = threadIdx.x;

    __shared__ float sP[TK][TM + 4];   // +4 pad keeps float4 alignment, spreads banks
    __shared__ float sV[TK][DD];
    __shared__ float sS[TM], sEs[TM], sFs[TM];

    if (tid < TM) {
        sS[tid]  = g_s[rb + tid];
        sEs[tid] = g_Es[rb + tid];
        sFs[tid] = g_Fs[rb + tid];
    }

    const int w  = tid >> 5;
    const int l  = tid & 31;
    const int rg = l & 15;                    // rows 4*rg .. 4*rg+3
    const int db = w * 16 + (l >> 4) * 8;     // 8 consecutive dims

    unsigned long long acc[4][4];
    #pragma unroll
    for (int i = 0; i < 4; i++)
        #pragma unroll
        for (int j = 0; j < 4; j++) acc[i][j] = 0ull;
    float den = 0.f;

    __syncthreads();

    const int jbase = jsp * JLEN;

    for (int tile = 0; tile < NTILES; ++tile) {
        const int j0 = jbase + tile * TK;

        // ---- phase 1: build P tile (no exp: precomputed factors) ----
        #pragma unroll
        for (int it = 0; it < (TM * TK) / 256; ++it) {   // 4 iters
            int idx = tid + it * 256;
            int r = idx >> 4;
            int k = idx & 15;
            int j = j0 + k;
            int av = adj[(size_t)(rb + r) * NN + j];
            float sum = sS[r] + g_t[j];
            float p = 0.f;
            if (av > 0)
                p = (sum >= 0.f) ? (sEs[r] * g_Et[j]) : (sFs[r] * g_Ft[j]);
            sP[k][r] = p;
        }
        // ---- stage V tile ----
        #pragma unroll
        for (int h = 0; h < 2; ++h) {
            int f = tid + h * 256;     // float4 index, 512 total
            int k  = f >> 5;
            int dq = f & 31;
            ((float4*)&sV[k][0])[dq] =
                *(const float4*)(g_V + (size_t)(j0 + k) * DD + dq * 4);
        }
        __syncthreads();

        // ---- row denominators (threads 0..63 own one row each) ----
        if (tid < TM) {
            float d0 = 0.f;
            #pragma unroll
            for (int k = 0; k < TK; ++k) d0 += sP[k][tid];
            den += d0;
        }

        // ---- phase 2: packed-f32x2 rank-1 accumulation ----
        #pragma unroll 4
        for (int k = 0; k < TK; ++k) {
            float4 pv = *(const float4*)&sP[k][4 * rg];
            unsigned long long p2[4];
            unsigned int u0 = __float_as_uint(pv.x);
            unsigned int u1 = __float_as_uint(pv.y);
            unsigned int u2 = __float_as_uint(pv.z);
            unsigned int u3 = __float_as_uint(pv.w);
            asm("mov.b64 %0, {%1,%1};" : "=l"(p2[0]) : "r"(u0));
            asm("mov.b64 %0, {%1,%1};" : "=l"(p2[1]) : "r"(u1));
            asm("mov.b64 %0, {%1,%1};" : "=l"(p2[2]) : "r"(u2));
            asm("mov.b64 %0, {%1,%1};" : "=l"(p2[3]) : "r"(u3));
            const ulonglong2* vp = (const ulonglong2*)&sV[k][db];
            ulonglong2 va = vp[0];
            ulonglong2 vb = vp[1];
            unsigned long long v2[4] = {va.x, va.y, vb.x, vb.y};
            #pragma unroll
            for (int rr = 0; rr < 4; ++rr)
                #pragma unroll
                for (int pp = 0; pp < 4; ++pp)
                    asm("fma.rn.f32x2 %0, %1, %2, %0;"
                        : "+l"(acc[rr][pp]) : "l"(p2[rr]), "l"(v2[pp]));
        }
        __syncthreads();
    }

    // ---- write partials ----
    float* outp = g_parts[jsp];
    #pragma unroll
    for (int rr = 0; rr < 4; ++rr) {
        size_t row = (size_t)(rb + 4 * rg + rr) * DD;
        #pragma unroll
        for (int pp = 0; pp < 4; ++pp)
            *(unsigned long long*)(outp + row + db + 2 * pp) = acc[rr][pp];
    }
    if (tid < TM) g_dparts[jsp][rb + tid] = den;
}

// ---------------- Kernel D: combine partials, normalize, relu ----------------
__global__ void k_final(float* __restrict__ out) {
    int idx = blockIdx.x * 256 + threadIdx.x;   // < NN*DD
    int r = idx >> 7;
    float dsum = g_dparts[0][r] + g_dparts[1][r] + g_dparts[2][r] + g_dparts[3][r];
    float v = g_parts[0][idx] + g_parts[1][idx] + g_parts[2][idx] + g_parts[3][idx];
    out[idx] = fmaxf(v / dsum, 0.f);
}

// ---------------- launch ----------------
extern "C" void kernel_launch(void* const* d_in, const int* in_sizes, int n_in,
                              void* d_out, int out_size) {
    const float* emb = (const float*)d_in[0];
    const int*   adj = (const int*)d_in[1];
    const float* W   = (const float*)d_in[2];
    const float* a   = (const float*)d_in[3];
    float* out = (float*)d_out;

    k_transW<<<(DD * DD + 255) / 256, 256>>>(W);
    k_enew<<<NN / 16, 256>>>(emb);
    k_scal<<<NN, 128>>>(a);
    dim3 gC(MTILES, JSPLIT);
    k_main<<<gC, 256>>>(adj);
    k_final<<<(NN * DD) / 256, 256>>>(out);
}

// round 4
// speedup vs baseline: 1.6679x; 1.6679x over previous
#include <cuda_runtime.h>
#include <cstdint>

#define NN 12288
#define DD 128
#define JSPLIT 3
#define JLEN (NN / JSPLIT)      // 4096
#define KC 32
#define NC (JLEN / KC)          // 128 chunks
#define MB 128
#define MBLK (NN / MB)          // 96

// ---------------- static scratch ----------------
__device__ float g_WT[DD * DD];
__device__ float g_V[(size_t)NN * DD];
__device__ float g_s[NN], g_t[NN];
__device__ float g_Es[NN], g_Et[NN], g_Fs[NN], g_Ft[NN];
__device__ float g_parts[JSPLIT][(size_t)NN * DD];
__device__ float g_dparts[JSPLIT][NN];

__device__ __forceinline__ float totf32(float x) {
    float r; asm("cvt.rna.tf32.f32 %0, %1;" : "=f"(r) : "f"(x)); return r;
}

__device__ __forceinline__ void mma_tf32_16x8x8(float* c, const float* a, const float* b) {
    asm volatile(
        "mma.sync.aligned.m16n8k8.row.col.f32.tf32.tf32.f32 "
        "{%0,%1,%2,%3}, {%4,%5,%6,%7}, {%8,%9}, {%0,%1,%2,%3};"
        : "+f"(c[0]), "+f"(c[1]), "+f"(c[2]), "+f"(c[3])
        : "f"(a[0]), "f"(a[1]), "f"(a[2]), "f"(a[3]), "f"(b[0]), "f"(b[1]));
}

// ---------------- Kernel A0: transpose W ----------------
__global__ void k_transW(const float* __restrict__ W) {
    int i = blockIdx.x * 256 + threadIdx.x;
    if (i < DD * DD) {
        int d = i >> 7, k = i & 127;
        g_WT[k * DD + d] = W[i];
    }
}

// ---------------- Kernel A: e_new = emb @ W^T ----------------
__global__ __launch_bounds__(256) void k_enew(const float* __restrict__ emb) {
    const int rb = blockIdx.x * 16;
    const int tid = threadIdx.x;
    __shared__ float es[16][128];
    for (int i = tid; i < 16 * 128; i += 256) {
        int r = i >> 7, k = i & 127;
        es[r][k] = emb[(size_t)(rb + r) * DD + k];
    }
    __syncthreads();
    const int rg = tid >> 5;
    const int dq = tid & 31;
    float acc[2][4];
    #pragma unroll
    for (int i = 0; i < 2; i++)
        #pragma unroll
        for (int j = 0; j < 4; j++) acc[i][j] = 0.f;
    #pragma unroll 4
    for (int k = 0; k < 128; ++k) {
        float4 wv = *(const float4*)&g_WT[k * DD + 4 * dq];
        float e0 = es[rg * 2 + 0][k];
        float e1 = es[rg * 2 + 1][k];
        acc[0][0] += e0 * wv.x; acc[0][1] += e0 * wv.y; acc[0][2] += e0 * wv.z; acc[0][3] += e0 * wv.w;
        acc[1][0] += e1 * wv.x; acc[1][1] += e1 * wv.y; acc[1][2] += e1 * wv.z; acc[1][3] += e1 * wv.w;
    }
    #pragma unroll
    for (int rr = 0; rr < 2; ++rr) {
        size_t row = (size_t)(rb + rg * 2 + rr) * DD;
        *(float4*)&g_V[row + 4 * dq] = make_float4(acc[rr][0], acc[rr][1], acc[rr][2], acc[rr][3]);
    }
}

// ---------------- Kernel B: per-row scalars ----------------
__global__ void k_scal(const float* __restrict__ a) {
    const int i = blockIdx.x;
    const int tid = threadIdx.x;  // 128
    float v = g_V[(size_t)i * DD + tid];
    float sp = v * a[tid];
    float tp = v * a[DD + tid];
    #pragma unroll
    for (int off = 16; off; off >>= 1) {
        sp += __shfl_down_sync(0xffffffffu, sp, off);
        tp += __shfl_down_sync(0xffffffffu, tp, off);
    }
    __shared__ float rs[4], rt[4];
    int w = tid >> 5;
    if ((tid & 31) == 0) { rs[w] = sp; rt[w] = tp; }
    __syncthreads();
    if (tid == 0) {
        float s = rs[0] + rs[1] + rs[2] + rs[3];
        float t = rt[0] + rt[1] + rt[2] + rt[3];
        g_s[i] = s; g_Es[i] = expf(s); g_Fs[i] = expf(0.01f * s);
        g_t[i] = t; g_Et[i] = expf(t); g_Ft[i] = expf(0.01f * t);
    }
}

// ---------------- Kernel C: mma.sync tf32  P @ V ----------------
// CTA: 128 rows x 128 dims, 256 threads = 8 warps.
// Warp w: rows [(w&3)*32, +32), dims [(w>>2)*64, +64).
// k loop: KC=32 nodes/chunk; 4 ksteps of 8 -> m16n8k8 tf32 mma.
__global__ __launch_bounds__(256) void k_mma(const int* __restrict__ adj) {
    __shared__ float sP[128][36];   // P tile [row][k], pad 36: bank=4r+k conflict-free
    __shared__ float sV[32][132];   // V tile [k][dim], pad 132: bank=4k+n conflict-free
    __shared__ float sDen[128];

    const int tid = threadIdx.x;
    const int w   = tid >> 5;
    const int l   = tid & 31;
    const int g   = l >> 2;      // group id 0..7
    const int t4  = l & 3;       // thread-in-group 0..3
    const int rb  = blockIdx.x * MB;
    const int jsp = blockIdx.y;

    const int mrow = (w & 3) * 32;     // warp row base
    const int ncol = (w >> 2) * 64;    // warp dim base

    // P-build mapping: 2 threads per row
    const int r = tid >> 1;
    const int h = tid & 1;
    const float rowS  = g_s [rb + r];
    const float rowEs = g_Es[rb + r];
    const float rowFs = g_Fs[rb + r];
    const size_t adjrow = (size_t)(rb + r) * NN;

    if (tid < 128) sDen[tid] = 0.f;

    float acc[2][8][4];   // [mtile][ntile][reg]
    #pragma unroll
    for (int m = 0; m < 2; m++)
        #pragma unroll
        for (int n = 0; n < 8; n++)
            #pragma unroll
            for (int i = 0; i < 4; i++) acc[m][n][i] = 0.f;

    const int jbase = jsp * JLEN;

    for (int c = 0; c < NC; ++c) {
        const int jb = jbase + c * KC;

        // ---- build P tile (factored exp, tf32-rounded) + row partial sums ----
        float psum = 0.f;
        #pragma unroll
        for (int q = 0; q < 4; ++q) {
            const int col = 16 * h + 4 * q;
            const int j   = jb + col;
            int4   av  = *(const int4*)(adj + adjrow + j);
            float4 tv  = *(const float4*)(g_t  + j);
            float4 etv = *(const float4*)(g_Et + j);
            float4 ftv = *(const float4*)(g_Ft + j);
            float p0 = (av.x > 0) ? ((rowS + tv.x >= 0.f) ? rowEs * etv.x : rowFs * ftv.x) : 0.f;
            float p1 = (av.y > 0) ? ((rowS + tv.y >= 0.f) ? rowEs * etv.y : rowFs * ftv.y) : 0.f;
            float p2 = (av.z > 0) ? ((rowS + tv.z >= 0.f) ? rowEs * etv.z : rowFs * ftv.z) : 0.f;
            float p3 = (av.w > 0) ? ((rowS + tv.w >= 0.f) ? rowEs * etv.w : rowFs * ftv.w) : 0.f;
            p0 = totf32(p0); p1 = totf32(p1); p2 = totf32(p2); p3 = totf32(p3);
            psum += (p0 + p1) + (p2 + p3);
            *(float4*)&sP[r][col] = make_float4(p0, p1, p2, p3);
        }
        psum += __shfl_down_sync(0xffffffffu, psum, 1);
        if (h == 0) sDen[r] += psum;

        // ---- stage V tile: sV[k][dim] = V[jb+k][dim]  (node-major rows, no transpose) ----
        #pragma unroll
        for (int it = 0; it < 4; ++it) {
            int f  = tid + it * 256;   // float4 index, 1024 total
            int k  = f >> 5;
            int dq = f & 31;
            float4 vv = *(const float4*)(g_V + (size_t)(jb + k) * DD + 4 * dq);
            vv.x = totf32(vv.x); vv.y = totf32(vv.y); vv.z = totf32(vv.z); vv.w = totf32(vv.w);
            *(float4*)&sV[k][4 * dq] = vv;
        }
        __syncthreads();

        // ---- tensor-core accumulation ----
        #pragma unroll
        for (int ks = 0; ks < 4; ++ks) {
            const int k0 = 8 * ks;
            float afrag[2][4];
            #pragma unroll
            for (int m = 0; m < 2; ++m) {
                const int r0 = mrow + 16 * m;
                afrag[m][0] = sP[r0 + g    ][k0 + t4    ];
                afrag[m][1] = sP[r0 + g + 8][k0 + t4    ];
                afrag[m][2] = sP[r0 + g    ][k0 + t4 + 4];
                afrag[m][3] = sP[r0 + g + 8][k0 + t4 + 4];
            }
            #pragma unroll
            for (int n = 0; n < 8; ++n) {
                const int n0 = ncol + 8 * n;
                float bfrag[2];
                bfrag[0] = sV[k0 + t4    ][n0 + g];
                bfrag[1] = sV[k0 + t4 + 4][n0 + g];
                mma_tf32_16x8x8(acc[0][n], afrag[0], bfrag);
                mma_tf32_16x8x8(acc[1][n], afrag[1], bfrag);
            }
        }
        __syncthreads();
    }

    // ---- epilogue: write C fragments + denominators ----
    float* outp = g_parts[jsp];
    #pragma unroll
    for (int m = 0; m < 2; ++m) {
        #pragma unroll
        for (int n = 0; n < 8; ++n) {
            const int row0 = rb + mrow + 16 * m + g;
            const int col  = ncol + 8 * n + 2 * t4;
            *(float2*)(outp + (size_t)row0 * DD + col) =
                make_float2(acc[m][n][0], acc[m][n][1]);
            *(float2*)(outp + (size_t)(row0 + 8) * DD + col) =
                make_float2(acc[m][n][2], acc[m][n][3]);
        }
    }
    if (tid < 128) g_dparts[jsp][rb + tid] = sDen[tid];
}

// ---------------- Kernel D: combine partials, normalize, relu ----------------
__global__ void k_final(float* __restrict__ out) {
    int idx = blockIdx.x * 256 + threadIdx.x;
    int r = idx >> 7;
    float dsum = g_dparts[0][r] + g_dparts[1][r] + g_dparts[2][r];
    float v = g_parts[0][idx] + g_parts[1][idx] + g_parts[2][idx];
    out[idx] = fmaxf(v / dsum, 0.f);
}

// ---------------- launch ----------------
extern "C" void kernel_launch(void* const* d_in, const int* in_sizes, int n_in,
                              void* d_out, int out_size) {
    const float* emb = (const float*)d_in[0];
    const int*   adj = (const int*)d_in[1];
    const float* W   = (const float*)d_in[2];
    const float* a   = (const float*)d_in[3];
    float* out = (float*)d_out;

    k_transW<<<(DD * DD + 255) / 256, 256>>>(W);
    k_enew<<<NN / 16, 256>>>(emb);
    k_scal<<<NN, 128>>>(a);
    k_mma<<<dim3(MBLK, JSPLIT), 256>>>(adj);
    k_final<<<(NN * DD) / 256, 256>>>(out);
}

// round 6
// speedup vs baseline: 2.5762x; 1.5445x over previous
#include <cuda_runtime.h>
#include <cstdint>

#define NN 12288
#define DD 128
#define JSPLIT 3
#define JLEN (NN / JSPLIT)      // 4096
#define KC 32
#define NC (JLEN / KC)          // 128 chunks
#define MB 128
#define MBLK (NN / MB)          // 96

// dynamic smem layout (floats)
#define SP_OFF   0                      // sP[128][36]
#define SV_OFF   (128 * 36)             // sV[2][32][132]
#define DEN_OFF  (SV_OFF + 2 * 32 * 132)
#define SMEM_FLOATS (DEN_OFF + 128)
#define SMEM_BYTES  (SMEM_FLOATS * 4)   // 52736

// ---------------- static scratch ----------------
__device__ float g_WT[DD * DD];
__device__ float g_V [(size_t)NN * DD];
__device__ float g_Vr[(size_t)NN * DD];            // tf32-pre-rounded V
__device__ float g_s[NN], g_t[NN];
__device__ float g_Es[NN], g_Et[NN], g_Fs[NN], g_Ft[NN];
__device__ float g_parts[JSPLIT][(size_t)NN * DD];
__device__ float g_dparts[JSPLIT][NN];

__device__ __forceinline__ float totf32(float x) {
    float r; asm("cvt.rna.tf32.f32 %0, %1;" : "=f"(r) : "f"(x)); return r;
}
__device__ __forceinline__ void mma_tf32_16x8x8(float* c, const float* a, const float* b) {
    asm volatile(
        "mma.sync.aligned.m16n8k8.row.col.f32.tf32.tf32.f32 "
        "{%0,%1,%2,%3}, {%4,%5,%6,%7}, {%8,%9}, {%0,%1,%2,%3};"
        : "+f"(c[0]), "+f"(c[1]), "+f"(c[2]), "+f"(c[3])
        : "f"(a[0]), "f"(a[1]), "f"(a[2]), "f"(a[3]), "f"(b[0]), "f"(b[1]));
}
__device__ __forceinline__ void cp_async16(uint32_t dst, const void* src) {
    asm volatile("cp.async.ca.shared.global [%0], [%1], 16;"
                 :: "r"(dst), "l"(src) : "memory");
}
__device__ __forceinline__ void cp_commit() {
    asm volatile("cp.async.commit_group;" ::: "memory");
}
__device__ __forceinline__ void cp_wait0() {
    asm volatile("cp.async.wait_group 0;" ::: "memory");
}
__device__ __forceinline__ void pf_l1(const void* p) {
    asm volatile("prefetch.global.L1 [%0];" :: "l"(p));
}

// ---------------- Kernel A0: transpose W ----------------
__global__ void k_transW(const float* __restrict__ W) {
    int i = blockIdx.x * 256 + threadIdx.x;
    if (i < DD * DD) {
        int d = i >> 7, k = i & 127;
        g_WT[k * DD + d] = W[i];
    }
}

// ---------------- Kernel A: e_new = emb @ W^T (+ tf32-rounded copy) ----------------
__global__ __launch_bounds__(256) void k_enew(const float* __restrict__ emb) {
    const int rb = blockIdx.x * 16;
    const int tid = threadIdx.x;
    __shared__ float es[16][128];
    for (int i = tid; i < 16 * 128; i += 256) {
        int r = i >> 7, k = i & 127;
        es[r][k] = emb[(size_t)(rb + r) * DD + k];
    }
    __syncthreads();
    const int rg = tid >> 5;
    const int dq = tid & 31;
    float acc[2][4];
    #pragma unroll
    for (int i = 0; i < 2; i++)
        #pragma unroll
        for (int j = 0; j < 4; j++) acc[i][j] = 0.f;
    #pragma unroll 4
    for (int k = 0; k < 128; ++k) {
        float4 wv = *(const float4*)&g_WT[k * DD + 4 * dq];
        float e0 = es[rg * 2 + 0][k];
        float e1 = es[rg * 2 + 1][k];
        acc[0][0] += e0 * wv.x; acc[0][1] += e0 * wv.y; acc[0][2] += e0 * wv.z; acc[0][3] += e0 * wv.w;
        acc[1][0] += e1 * wv.x; acc[1][1] += e1 * wv.y; acc[1][2] += e1 * wv.z; acc[1][3] += e1 * wv.w;
    }
    #pragma unroll
    for (int rr = 0; rr < 2; ++rr) {
        size_t row = (size_t)(rb + rg * 2 + rr) * DD;
        *(float4*)&g_V[row + 4 * dq] = make_float4(acc[rr][0], acc[rr][1], acc[rr][2], acc[rr][3]);
        *(float4*)&g_Vr[row + 4 * dq] = make_float4(totf32(acc[rr][0]), totf32(acc[rr][1]),
                                                    totf32(acc[rr][2]), totf32(acc[rr][3]));
    }
}

// ---------------- Kernel B: per-row scalars ----------------
__global__ void k_scal(const float* __restrict__ a) {
    const int i = blockIdx.x;
    const int tid = threadIdx.x;  // 128
    float v = g_V[(size_t)i * DD + tid];
    float sp = v * a[tid];
    float tp = v * a[DD + tid];
    #pragma unroll
    for (int off = 16; off; off >>= 1) {
        sp += __shfl_down_sync(0xffffffffu, sp, off);
        tp += __shfl_down_sync(0xffffffffu, tp, off);
    }
    __shared__ float rs[4], rt[4];
    int w = tid >> 5;
    if ((tid & 31) == 0) { rs[w] = sp; rt[w] = tp; }
    __syncthreads();
    if (tid == 0) {
        float s = rs[0] + rs[1] + rs[2] + rs[3];
        float t = rt[0] + rt[1] + rt[2] + rt[3];
        g_s[i] = s; g_Es[i] = expf(s); g_Fs[i] = expf(0.01f * s);
        g_t[i] = t; g_Et[i] = expf(t); g_Ft[i] = expf(0.01f * t);
    }
}

// ---------------- Kernel C: pipelined mma.sync tf32  P @ V ----------------
__global__ __launch_bounds__(256) void k_mma(const int* __restrict__ adj) {
    extern __shared__ float smemf[];
    float (*sP)[36]      = (float (*)[36])(smemf + SP_OFF);
    float (*sV)[32][132] = (float (*)[32][132])(smemf + SV_OFF);
    float* sDen          = smemf + DEN_OFF;
    const uint32_t sv_base = (uint32_t)__cvta_generic_to_shared(smemf + SV_OFF);

    const int tid = threadIdx.x;
    const int w   = tid >> 5;
    const int l   = tid & 31;
    const int g   = l >> 2;
    const int t4  = l & 3;
    const int rb  = blockIdx.x * MB;
    const int jsp = blockIdx.y;

    const int mrow = (w & 3) * 32;
    const int ncol = (w >> 2) * 64;

    const int r = tid >> 1;
    const int h = tid & 1;
    const float rowS  = g_s [rb + r];
    const float rowEs = g_Es[rb + r];
    const float rowFs = g_Fs[rb + r];
    const size_t adjrow = (size_t)(rb + r) * NN;

    float denreg = 0.f;   // register den accumulator (owned by h==0 thread of row r)

    float acc[2][8][4];
    #pragma unroll
    for (int m = 0; m < 2; m++)
        #pragma unroll
        for (int n = 0; n < 8; n++)
            #pragma unroll
            for (int i = 0; i < 4; i++) acc[m][n][i] = 0.f;

    const int jbase = jsp * JLEN;

    // ---- helpers ----
    #define STAGE_V(jb_, buf_)                                                    \
        {                                                                         \
            _Pragma("unroll")                                                     \
            for (int it = 0; it < 4; ++it) {                                      \
                int f_ = tid + it * 256;                                          \
                int k_ = f_ >> 5, dq_ = f_ & 31;                                  \
                uint32_t dst_ = sv_base + (uint32_t)(((buf_) * 32 + k_) * 132 + 4 * dq_) * 4u; \
                cp_async16(dst_, g_Vr + (size_t)((jb_) + k_) * DD + 4 * dq_);     \
            }                                                                     \
            cp_commit();                                                          \
        }

    #define BUILD_P(jb_, A4_)                                                     \
        {                                                                         \
            float psum_ = 0.f;                                                    \
            _Pragma("unroll")                                                     \
            for (int q_ = 0; q_ < 4; ++q_) {                                      \
                const int col_ = 16 * h + 4 * q_;                                 \
                const int j_   = (jb_) + col_;                                    \
                int4   av  = A4_[q_];                                             \
                float4 tv  = *(const float4*)(g_t  + j_);                         \
                float4 etv = *(const float4*)(g_Et + j_);                         \
                float4 ftv = *(const float4*)(g_Ft + j_);                         \
                float p0 = (av.x > 0) ? ((rowS + tv.x >= 0.f) ? rowEs * etv.x : rowFs * ftv.x) : 0.f; \
                float p1 = (av.y > 0) ? ((rowS + tv.y >= 0.f) ? rowEs * etv.y : rowFs * ftv.y) : 0.f; \
                float p2 = (av.z > 0) ? ((rowS + tv.z >= 0.f) ? rowEs * etv.z : rowFs * ftv.z) : 0.f; \
                float p3 = (av.w > 0) ? ((rowS + tv.w >= 0.f) ? rowEs * etv.w : rowFs * ftv.w) : 0.f; \
                p0 = totf32(p0); p1 = totf32(p1); p2 = totf32(p2); p3 = totf32(p3); \
                psum_ += (p0 + p1) + (p2 + p3);                                   \
                *(float4*)&sP[r][col_] = make_float4(p0, p1, p2, p3);             \
            }                                                                     \
            psum_ += __shfl_down_sync(0xffffffffu, psum_, 1);                     \
            if (h == 0) denreg += psum_;                                          \
        }

    // ---- prologue: chunk 0 tiles ----
    int4 a4[4];
    {
        const int jb0 = jbase;
        STAGE_V(jb0, 0);
        #pragma unroll
        for (int q = 0; q < 4; ++q)
            a4[q] = *(const int4*)(adj + adjrow + jb0 + 16 * h + 4 * q);
        BUILD_P(jb0, a4);
        cp_wait0();
        __syncthreads();
        // V(1) in flight during chunk-0 MMA
        STAGE_V(jbase + KC, 1);
        // prefetch adj(1)
        #pragma unroll
        for (int q = 0; q < 4; ++q)
            a4[q] = *(const int4*)(adj + adjrow + jbase + KC + 16 * h + 4 * q);
    }

    for (int c = 0; c < NC; ++c) {
        const int buf = c & 1;

        // L1 prefetch of next chunk's scalar arrays
        if (c + 1 < NC && w == 0) {
            const int jn = jbase + (c + 1) * KC + 16 * h;
            pf_l1(g_t + jn); pf_l1(g_Et + jn); pf_l1(g_Ft + jn);
        }

        // ---- MMA phase on chunk c ----
        #pragma unroll
        for (int ks = 0; ks < 4; ++ks) {
            const int k0 = 8 * ks;
            float afrag[2][4];
            #pragma unroll
            for (int m = 0; m < 2; ++m) {
                const int r0 = mrow + 16 * m;
                afrag[m][0] = sP[r0 + g    ][k0 + t4    ];
                afrag[m][1] = sP[r0 + g + 8][k0 + t4    ];
                afrag[m][2] = sP[r0 + g    ][k0 + t4 + 4];
                afrag[m][3] = sP[r0 + g + 8][k0 + t4 + 4];
            }
            #pragma unroll
            for (int n = 0; n < 8; ++n) {
                const int n0 = ncol + 8 * n;
                float bfrag[2];
                bfrag[0] = sV[buf][k0 + t4    ][n0 + g];
                bfrag[1] = sV[buf][k0 + t4 + 4][n0 + g];
                mma_tf32_16x8x8(acc[0][n], afrag[0], bfrag);
                mma_tf32_16x8x8(acc[1][n], afrag[1], bfrag);
            }
        }

        if (c + 1 < NC) {
            cp_wait0();          // V(c+1) (overlapped with MMA above)
            __syncthreads();     // all warps done reading P(c)/V(c); V(c+1) visible
            BUILD_P(jbase + (c + 1) * KC, a4);
            if (c + 2 < NC) {
                STAGE_V(jbase + (c + 2) * KC, buf);   // reuse freed buffer
                #pragma unroll
                for (int q = 0; q < 4; ++q)
                    a4[q] = *(const int4*)(adj + adjrow + jbase + (c + 2) * KC + 16 * h + 4 * q);
            }
            __syncthreads();     // P(c+1) ready
        }
    }

    // ---- epilogue ----
    float* outp = g_parts[jsp];
    #pragma unroll
    for (int m = 0; m < 2; ++m) {
        #pragma unroll
        for (int n = 0; n < 8; ++n) {
            const int row0 = rb + mrow + 16 * m + g;
            const int col  = ncol + 8 * n + 2 * t4;
            *(float2*)(outp + (size_t)row0 * DD + col) =
                make_float2(acc[m][n][0], acc[m][n][1]);
            *(float2*)(outp + (size_t)(row0 + 8) * DD + col) =
                make_float2(acc[m][n][2], acc[m][n][3]);
        }
    }
    __syncthreads();             // all tile traffic done; sDen free to use
    if (h == 0) sDen[r] = denreg;
    __syncthreads();
    if (tid < 128) g_dparts[jsp][rb + tid] = sDen[tid];
}

// ---------------- Kernel D: combine partials, normalize, relu ----------------
__global__ void k_final(float* __restrict__ out) {
    int idx = blockIdx.x * 256 + threadIdx.x;
    int r = idx >> 7;
    float dsum = g_dparts[0][r] + g_dparts[1][r] + g_dparts[2][r];
    float v = g_parts[0][idx] + g_parts[1][idx] + g_parts[2][idx];
    out[idx] = fmaxf(v / dsum, 0.f);
}

// ---------------- launch ----------------
extern "C" void kernel_launch(void* const* d_in, const int* in_sizes, int n_in,
                              void* d_out, int out_size) {
    const float* emb = (const float*)d_in[0];
    const int*   adj = (const int*)d_in[1];
    const float* W   = (const float*)d_in[2];
    const float* a   = (const float*)d_in[3];
    float* out = (float*)d_out;

    cudaFuncSetAttribute(k_mma, cudaFuncAttributeMaxDynamicSharedMemorySize, SMEM_BYTES);

    k_transW<<<(DD * DD + 255) / 256, 256>>>(W);
    k_enew<<<NN / 16, 256>>>(emb);
    k_scal<<<NN, 128>>>(a);
    k_mma<<<dim3(MBLK, JSPLIT), 256, SMEM_BYTES>>>(adj);
    k_final<<<(NN * DD) / 256, 256>>>(out);
}

// round 7
// speedup vs baseline: 3.0340x; 1.1777x over previous
#include <cuda_runtime.h>
#include <cstdint>

#define NN 12288
#define DD 128
#define JSPLIT 3
#define JLEN (NN / JSPLIT)      // 4096
#define KC 32
#define NC (JLEN / KC)          // 128 chunks
#define MB 128
#define MBLK (NN / MB)          // 96

// dynamic smem layout (floats)
#define SP_OFF   0                          // sP[2][128][36]
#define SV_OFF   (2 * 128 * 36)             // sV[2][32][136]
#define DEN_OFF  (SV_OFF + 2 * 32 * 136)
#define SMEM_FLOATS (DEN_OFF + 128)
#define SMEM_BYTES  (SMEM_FLOATS * 4)       // 72192 B

// ---------------- static scratch ----------------
__device__ float g_WT[DD * DD];
__device__ float g_V [(size_t)NN * DD];
__device__ float g_Vr[(size_t)NN * DD];            // tf32-pre-rounded V
__device__ float g_s[NN], g_t[NN];
__device__ float g_Es[NN], g_Et[NN], g_Fs[NN], g_Ft[NN];
__device__ float g_parts[JSPLIT][(size_t)NN * DD];
__device__ float g_dparts[JSPLIT][NN];

__device__ __forceinline__ float totf32(float x) {
    float r; asm("cvt.rna.tf32.f32 %0, %1;" : "=f"(r) : "f"(x)); return r;
}
__device__ __forceinline__ void mma_tf32_16x8x8(float* c, const float* a, const float* b) {
    asm volatile(
        "mma.sync.aligned.m16n8k8.row.col.f32.tf32.tf32.f32 "
        "{%0,%1,%2,%3}, {%4,%5,%6,%7}, {%8,%9}, {%0,%1,%2,%3};"
        : "+f"(c[0]), "+f"(c[1]), "+f"(c[2]), "+f"(c[3])
        : "f"(a[0]), "f"(a[1]), "f"(a[2]), "f"(a[3]), "f"(b[0]), "f"(b[1]));
}
__device__ __forceinline__ void cp_async16(uint32_t dst, const void* src) {
    asm volatile("cp.async.ca.shared.global [%0], [%1], 16;"
                 :: "r"(dst), "l"(src) : "memory");
}
__device__ __forceinline__ void cp_commit() {
    asm volatile("cp.async.commit_group;" ::: "memory");
}
__device__ __forceinline__ void cp_wait0() {
    asm volatile("cp.async.wait_group 0;" ::: "memory");
}
__device__ __forceinline__ void pf_l1(const void* p) {
    asm volatile("prefetch.global.L1 [%0];" :: "l"(p));
}

// ---------------- Kernel A0: transpose W ----------------
__global__ void k_transW(const float* __restrict__ W) {
    int i = blockIdx.x * 256 + threadIdx.x;
    if (i < DD * DD) {
        int d = i >> 7, k = i & 127;
        g_WT[k * DD + d] = W[i];
    }
}

// ---------------- Kernel A: e_new = emb @ W^T (+ tf32-rounded copy) ----------------
__global__ __launch_bounds__(256) void k_enew(const float* __restrict__ emb) {
    const int rb = blockIdx.x * 16;
    const int tid = threadIdx.x;
    __shared__ float es[16][128];
    for (int i = tid; i < 16 * 128; i += 256) {
        int r = i >> 7, k = i & 127;
        es[r][k] = emb[(size_t)(rb + r) * DD + k];
    }
    __syncthreads();
    const int rg = tid >> 5;
    const int dq = tid & 31;
    float acc[2][4];
    #pragma unroll
    for (int i = 0; i < 2; i++)
        #pragma unroll
        for (int j = 0; j < 4; j++) acc[i][j] = 0.f;
    #pragma unroll 4
    for (int k = 0; k < 128; ++k) {
        float4 wv = *(const float4*)&g_WT[k * DD + 4 * dq];
        float e0 = es[rg * 2 + 0][k];
        float e1 = es[rg * 2 + 1][k];
        acc[0][0] += e0 * wv.x; acc[0][1] += e0 * wv.y; acc[0][2] += e0 * wv.z; acc[0][3] += e0 * wv.w;
        acc[1][0] += e1 * wv.x; acc[1][1] += e1 * wv.y; acc[1][2] += e1 * wv.z; acc[1][3] += e1 * wv.w;
    }
    #pragma unroll
    for (int rr = 0; rr < 2; ++rr) {
        size_t row = (size_t)(rb + rg * 2 + rr) * DD;
        *(float4*)&g_V[row + 4 * dq] = make_float4(acc[rr][0], acc[rr][1], acc[rr][2], acc[rr][3]);
        *(float4*)&g_Vr[row + 4 * dq] = make_float4(totf32(acc[rr][0]), totf32(acc[rr][1]),
                                                    totf32(acc[rr][2]), totf32(acc[rr][3]));
    }
}

// ---------------- Kernel B: per-row scalars ----------------
__global__ void k_scal(const float* __restrict__ a) {
    const int i = blockIdx.x;
    const int tid = threadIdx.x;  // 128
    float v = g_V[(size_t)i * DD + tid];
    float sp = v * a[tid];
    float tp = v * a[DD + tid];
    #pragma unroll
    for (int off = 16; off; off >>= 1) {
        sp += __shfl_down_sync(0xffffffffu, sp, off);
        tp += __shfl_down_sync(0xffffffffu, tp, off);
    }
    __shared__ float rs[4], rt[4];
    int w = tid >> 5;
    if ((tid & 31) == 0) { rs[w] = sp; rt[w] = tp; }
    __syncthreads();
    if (tid == 0) {
        float s = rs[0] + rs[1] + rs[2] + rs[3];
        float t = rt[0] + rt[1] + rt[2] + rt[3];
        g_s[i] = s; g_Es[i] = expf(s); g_Fs[i] = expf(0.01f * s);
        g_t[i] = t; g_Et[i] = expf(t); g_Ft[i] = expf(0.01f * t);
    }
}

// ---------------- Kernel C: pipelined mma.sync tf32  P @ V ----------------
// Double-buffered P AND V; one __syncthreads per chunk.
// Chunk c: P in sPb[c&1], V in sVb[c&1]. Build(c+1) overlaps MMA(c).
__global__ __launch_bounds__(256, 2) void k_mma(const int* __restrict__ adj) {
    extern __shared__ float smemf[];
    float (*sPb)[128][36]  = (float (*)[128][36])(smemf + SP_OFF);
    float (*sVb)[32][136]  = (float (*)[32][136])(smemf + SV_OFF);
    float* sDen            = smemf + DEN_OFF;
    const uint32_t sv_base = (uint32_t)__cvta_generic_to_shared(smemf + SV_OFF);

    const int tid = threadIdx.x;
    const int w   = tid >> 5;
    const int l   = tid & 31;
    const int g   = l >> 2;
    const int t4  = l & 3;
    const int rb  = blockIdx.x * MB;
    const int jsp = blockIdx.y;

    const int mrow = (w & 3) * 32;
    const int ncol = (w >> 2) * 64;

    const int r = tid >> 1;
    const int h = tid & 1;
    const float rowS  = g_s [rb + r];
    const float rowEs = g_Es[rb + r];
    const float rowFs = g_Fs[rb + r];
    const size_t adjrow = (size_t)(rb + r) * NN;

    float denreg = 0.f;

    float acc[2][8][4];
    #pragma unroll
    for (int m = 0; m < 2; m++)
        #pragma unroll
        for (int n = 0; n < 8; n++)
            #pragma unroll
            for (int i = 0; i < 4; i++) acc[m][n][i] = 0.f;

    const int jbase = jsp * JLEN;

    #define STAGE_V(jb_, buf_)                                                    \
        {                                                                         \
            _Pragma("unroll")                                                     \
            for (int it = 0; it < 4; ++it) {                                      \
                int f_ = tid + it * 256;                                          \
                int k_ = f_ >> 5, dq_ = f_ & 31;                                  \
                uint32_t dst_ = sv_base + (uint32_t)(((buf_) * 32 + k_) * 136 + 4 * dq_) * 4u; \
                cp_async16(dst_, g_Vr + (size_t)((jb_) + k_) * DD + 4 * dq_);     \
            }                                                                     \
            cp_commit();                                                          \
        }

    #define BUILD_P(jb_, A4_, pb_)                                                \
        {                                                                         \
            float psum_ = 0.f;                                                    \
            _Pragma("unroll")                                                     \
            for (int q_ = 0; q_ < 4; ++q_) {                                      \
                const int col_ = 16 * h + 4 * q_;                                 \
                const int j_   = (jb_) + col_;                                    \
                int4   av  = A4_[q_];                                             \
                float4 tv  = *(const float4*)(g_t  + j_);                         \
                float4 etv = *(const float4*)(g_Et + j_);                         \
                float4 ftv = *(const float4*)(g_Ft + j_);                         \
                float p0 = (av.x > 0) ? ((rowS + tv.x >= 0.f) ? rowEs * etv.x : rowFs * ftv.x) : 0.f; \
                float p1 = (av.y > 0) ? ((rowS + tv.y >= 0.f) ? rowEs * etv.y : rowFs * ftv.y) : 0.f; \
                float p2 = (av.z > 0) ? ((rowS + tv.z >= 0.f) ? rowEs * etv.z : rowFs * ftv.z) : 0.f; \
                float p3 = (av.w > 0) ? ((rowS + tv.w >= 0.f) ? rowEs * etv.w : rowFs * ftv.w) : 0.f; \
                p0 = totf32(p0); p1 = totf32(p1); p2 = totf32(p2); p3 = totf32(p3); \
                psum_ += (p0 + p1) + (p2 + p3);                                   \
                *(float4*)&sPb[pb_][r][col_] = make_float4(p0, p1, p2, p3);       \
            }                                                                     \
            psum_ += __shfl_down_sync(0xffffffffu, psum_, 1);                     \
            if (h == 0) denreg += psum_;                                          \
        }

    // ---- prologue: chunks 0 and 1 ----
    int4 a4[4];
    {
        STAGE_V(jbase, 0);                 // V(0) -> sVb[0]
        #pragma unroll
        for (int q = 0; q < 4; ++q)
            a4[q] = *(const int4*)(adj + adjrow + jbase + 16 * h + 4 * q);
        BUILD_P(jbase, a4, 0);             // P(0) -> sPb[0]
        STAGE_V(jbase + KC, 1);            // V(1) -> sVb[1]
        #pragma unroll
        for (int q = 0; q < 4; ++q)
            a4[q] = *(const int4*)(adj + adjrow + jbase + KC + 16 * h + 4 * q);
        cp_wait0();                        // V(0), V(1) landed
        __syncthreads();
    }

    for (int c = 0; c < NC; ++c) {
        const int buf = c & 1;

        // ---- overlapped build of P(c+1) into the other buffer ----
        if (c + 1 < NC) {
            BUILD_P(jbase + (c + 1) * KC, a4, buf ^ 1);
            if (c + 2 < NC) {
                if (w == 0) {
                    const int jn = jbase + (c + 2) * KC + 16 * h;
                    pf_l1(g_t + jn); pf_l1(g_Et + jn); pf_l1(g_Ft + jn);
                }
                #pragma unroll
                for (int q = 0; q < 4; ++q)
                    a4[q] = *(const int4*)(adj + adjrow + jbase + (c + 2) * KC + 16 * h + 4 * q);
            }
        }

        // ---- MMA phase on chunk c ----
        #pragma unroll
        for (int ks = 0; ks < 4; ++ks) {
            const int k0 = 8 * ks;
            float afrag[2][4];
            #pragma unroll
            for (int m = 0; m < 2; ++m) {
                const int r0 = mrow + 16 * m;
                afrag[m][0] = sPb[buf][r0 + g    ][k0 + t4    ];
                afrag[m][1] = sPb[buf][r0 + g + 8][k0 + t4    ];
                afrag[m][2] = sPb[buf][r0 + g    ][k0 + t4 + 4];
                afrag[m][3] = sPb[buf][r0 + g + 8][k0 + t4 + 4];
            }
            #pragma unroll
            for (int n = 0; n < 8; ++n) {
                const int n0 = ncol + 8 * n;
                float bfrag[2];
                bfrag[0] = sVb[buf][k0 + t4    ][n0 + g];
                bfrag[1] = sVb[buf][k0 + t4 + 4][n0 + g];
                mma_tf32_16x8x8(acc[0][n], afrag[0], bfrag);
                mma_tf32_16x8x8(acc[1][n], afrag[1], bfrag);
            }
        }

        if (c + 1 < NC) {
            cp_wait0();          // V(c+1) landed (staged at iter c-1)
            __syncthreads();     // publishes P(c+1), V(c+1); all reads of buf done
            if (c + 2 < NC)
                STAGE_V(jbase + (c + 2) * KC, buf);   // reuse freed V buffer
        }
    }

    // ---- epilogue ----
    float* outp = g_parts[jsp];
    #pragma unroll
    for (int m = 0; m < 2; ++m) {
        #pragma unroll
        for (int n = 0; n < 8; ++n) {
            const int row0 = rb + mrow + 16 * m + g;
            const int col  = ncol + 8 * n + 2 * t4;
            *(float2*)(outp + (size_t)row0 * DD + col) =
                make_float2(acc[m][n][0], acc[m][n][1]);
            *(float2*)(outp + (size_t)(row0 + 8) * DD + col) =
                make_float2(acc[m][n][2], acc[m][n][3]);
        }
    }
    __syncthreads();
    if (h == 0) sDen[r] = denreg;
    __syncthreads();
    if (tid < 128) g_dparts[jsp][rb + tid] = sDen[tid];
}

// ---------------- Kernel D: combine partials, normalize, relu ----------------
__global__ void k_final(float* __restrict__ out) {
    int idx = blockIdx.x * 256 + threadIdx.x;
    int r = idx >> 7;
    float dsum = g_dparts[0][r] + g_dparts[1][r] + g_dparts[2][r];
    float v = g_parts[0][idx] + g_parts[1][idx] + g_parts[2][idx];
    out[idx] = fmaxf(v / dsum, 0.f);
}

// ---------------- launch ----------------
extern "C" void kernel_launch(void* const* d_in, const int* in_sizes, int n_in,
                              void* d_out, int out_size) {
    const float* emb = (const float*)d_in[0];
    const int*   adj = (const int*)d_in[1];
    const float* W   = (const float*)d_in[2];
    const float* a   = (const float*)d_in[3];
    float* out = (float*)d_out;

    cudaFuncSetAttribute(k_mma, cudaFuncAttributeMaxDynamicSharedMemorySize, SMEM_BYTES);

    k_transW<<<(DD * DD + 255) / 256, 256>>>(W);
    k_enew<<<NN / 16, 256>>>(emb);
    k_scal<<<NN, 128>>>(a);
    k_mma<<<dim3(MBLK, JSPLIT), 256, SMEM_BYTES>>>(adj);
    k_final<<<(NN * DD) / 256, 256>>>(out);
}